// round 14
// baseline (speedup 1.0000x reference)
#include <cuda_runtime.h>
#include <cuda_fp16.h>
#include <cstdint>

#define B_   64
#define NR_  16384
#define IC_  16
#define NC_  10
#define OC_  16
#define CO_  160
#define KB   32
#define SMAX 19              // max splits per i (i<8: 19, i>=8: 18)

// -------- device scratch (no allocations allowed) --------
__device__ __half g_xhi[(size_t)IC_*B_*NR_];            // x hi fp16 [i][b][r]
__device__ __half g_xlo[(size_t)IC_*B_*NR_];            // x residual fp16
__device__ float g_part[(size_t)SMAX*B_*IC_*CO_];       // split-K partials [s][b][i][co]
__device__ float g_fcp[NC_*B_];                         // fc partial dots [c][b]
__device__ int   g_ctr = 0;

// GEMM smem byte offsets (rows padded to 40 halves = 80B)
#define WSH_OFF 0            // W hi: 2 stages x 160x40 halves
#define WSL_OFF 25600        // W lo
#define XSH_OFF 51200        // x hi: 3 stages x 64x40 halves
#define XSL_OFF 66560        // x lo
#define SMEM_G  81920

static __device__ __forceinline__ void mma16816(float* c, const uint32_t* a,
                                                const uint32_t* b) {
    asm volatile(
        "mma.sync.aligned.m16n8k16.row.col.f32.f16.f16.f32 "
        "{%0,%1,%2,%3}, {%4,%5,%6,%7}, {%8,%9}, {%0,%1,%2,%3};"
        : "+f"(c[0]), "+f"(c[1]), "+f"(c[2]), "+f"(c[3])
        : "r"(a[0]), "r"(a[1]), "r"(a[2]), "r"(a[3]), "r"(b[0]), "r"(b[1]));
}
// fp16-accumulator variant (corrections)
static __device__ __forceinline__ void mma16816h(uint32_t* c, const uint32_t* a,
                                                 const uint32_t* b) {
    asm volatile(
        "mma.sync.aligned.m16n8k16.row.col.f16.f16.f16.f16 "
        "{%0,%1}, {%2,%3,%4,%5}, {%6,%7}, {%0,%1};"
        : "+r"(c[0]), "+r"(c[1])
        : "r"(a[0]), "r"(a[1]), "r"(a[2]), "r"(a[3]), "r"(b[0]), "r"(b[1]));
}
static __device__ __forceinline__ void ldsm4(uint32_t* r, uint32_t addr) {
    asm volatile("ldmatrix.sync.aligned.m8n8.x4.shared.b16 {%0,%1,%2,%3}, [%4];"
                 : "=r"(r[0]), "=r"(r[1]), "=r"(r[2]), "=r"(r[3]) : "r"(addr));
}
static __device__ __forceinline__ void ldsm2(uint32_t* r, uint32_t addr) {
    asm volatile("ldmatrix.sync.aligned.m8n8.x2.shared.b16 {%0,%1}, [%2];"
                 : "=r"(r[0]), "=r"(r[1]) : "r"(addr));
}
static __device__ __forceinline__ uint32_t smem_u32(const void* p) {
    uint32_t a;
    asm("{ .reg .u64 t; cvta.to.shared.u64 t, %1; cvt.u32.u64 %0, t; }"
        : "=r"(a) : "l"(p));
    return a;
}
static __device__ __forceinline__ void cp16(uint32_t dst, const void* src) {
    asm volatile("cp.async.cg.shared.global [%0], [%1], 16;" :: "r"(dst), "l"(src));
}
static __device__ __forceinline__ void cp_commit() {
    asm volatile("cp.async.commit_group;" ::: "memory");
}
template <int N> static __device__ __forceinline__ void cp_wait() {
    asm volatile("cp.async.wait_group %0;" :: "n"(N) : "memory");
}
static __device__ __forceinline__ void hsplit(float v, __half& h, __half& l) {
    h = __float2half_rn(v);
    l = __float2half_rn(v - __half2float(h));
}

// ---------------------------------------------------------------------------
// 1) Transpose + fp16 hi/lo split: x[b][r][i] -> g_xhi/g_xlo [i][b][r]
// ---------------------------------------------------------------------------
__global__ void k_transpose(const float* __restrict__ x) {
    __shared__ float tile[16][64];
    const int b = blockIdx.y, tid = threadIdx.x;
    const int r = tid >> 2, i4 = (tid & 3) * 4;
    const int i = tid >> 4, rs = (tid & 15) * 4;
    for (int tt = 0; tt < 4; tt++) {
        const int r0 = (blockIdx.x * 4 + tt) * 64;
        float4 v = *(const float4*)(x + ((size_t)b * NR_ + r0 + r) * IC_ + i4);
        tile[i4 + 0][r] = v.x; tile[i4 + 1][r] = v.y;
        tile[i4 + 2][r] = v.z; tile[i4 + 3][r] = v.w;
        __syncthreads();
        float4 o = *(const float4*)&tile[i][rs];
        union { __half h[4]; uint2 u; } ph, pl;
        hsplit(o.x, ph.h[0], pl.h[0]);
        hsplit(o.y, ph.h[1], pl.h[1]);
        hsplit(o.z, ph.h[2], pl.h[2]);
        hsplit(o.w, ph.h[3], pl.h[3]);
        const size_t dst = ((size_t)i * B_ + b) * NR_ + r0 + rs;
        *(uint2*)(g_xhi + dst) = ph.u;
        *(uint2*)(g_xlo + dst) = pl.u;
        __syncthreads();
    }
}

// ---------------------------------------------------------------------------
// 2) fp16x3 HMMA GEMM, 296 balanced CTAs, ONE sync per chunk:
//    W(n+1) conversion is interleaved into the MMA(n) phase.
// ---------------------------------------------------------------------------
__global__ __launch_bounds__(256, 2) void k_gemm(const float* __restrict__ Wg) {
    extern __shared__ char smem[];
    const uint32_t sb = smem_u32(smem);

    // CTA -> (i, split j, chunk range)
    int i, j, nch, st;
    {
        const int c = blockIdx.x;
        if (c < 152) {           // 8 i's x 19 splits
            i = c / 19; j = c - i * 19;
            nch = 26 + (j < 18); st = j * 26 + min(j, 18);
        } else {                 // 8 i's x 18 splits
            const int d = c - 152;
            const int q = d / 18;
            i = 8 + q; j = d - q * 18;
            nch = 28 + (j < 8);  st = j * 28 + min(j, 8);
        }
    }
    const int r0 = st * KB;
    const int t = threadIdx.x;
    const int warp = t >> 5, lane = t & 31;
    const int wm = warp >> 2, wn = warp & 3;
    const float* Wi = Wg + (size_t)i * CO_ * NR_;
    const __half* Xh = g_xhi + (size_t)i * B_ * NR_;
    const __half* Xl = g_xlo + (size_t)i * B_ * NR_;

    float acc[2][5][4];
    uint32_t accC[2][5][2];
#pragma unroll
    for (int m = 0; m < 2; m++)
#pragma unroll
        for (int n = 0; n < 5; n++) {
#pragma unroll
            for (int q = 0; q < 4; q++) acc[m][n][q] = 0.f;
            accC[m][n][0] = 0u; accC[m][n][1] = 0u;
        }

    const int tA = lane >> 3;
    const int a_ml = (tA & 1) * 8 + (lane & 7);
    const int a_ko = (tA >> 1) * 8;
    const int b_bn = lane & 7;
    const int b_ko = (tA & 1) * 8;
    const int b_p  = tA >> 1;
    const int tC   = (lane >> 3) & 1;

    const int wrow = t >> 3, wk4 = t & 7;
    float4 wr[5];

#define LDGW(nn) { \
        const float* wp = Wi + (size_t)wrow * NR_ + r0 + (nn) * KB + wk4 * 4; \
        _Pragma("unroll") \
        for (int q = 0; q < 5; q++) wr[q] = *(const float4*)(wp + (size_t)q * 32 * NR_); }

// convert wr -> W smem stage ss
#define CONVW(ss) { \
        _Pragma("unroll") \
        for (int q = 0; q < 5; q++) { \
            union { __half h[4]; uint2 u; } ph, pl; \
            hsplit(wr[q].x, ph.h[0], pl.h[0]); \
            hsplit(wr[q].y, ph.h[1], pl.h[1]); \
            hsplit(wr[q].z, ph.h[2], pl.h[2]); \
            hsplit(wr[q].w, ph.h[3], pl.h[3]); \
            const uint32_t d = (uint32_t)(((wrow + q * 32) * 40 + wk4 * 4) * 2) \
                             + (ss) * 12800; \
            *(uint2*)(smem + WSH_OFF + d) = ph.u; \
            *(uint2*)(smem + WSL_OFF + d) = pl.u; \
        } }

#define XCP(nn, ss) { \
        const int xrow = t >> 2, xk8 = (t & 3) * 8; \
        const size_t so = (size_t)xrow * NR_ + r0 + (nn) * KB + xk8; \
        const uint32_t d = (uint32_t)((xrow * 40 + xk8) * 2) + (ss) * 5120; \
        cp16(sb + XSH_OFF + d, Xh + so); \
        cp16(sb + XSL_OFF + d, Xl + so); \
        cp_commit(); }

    // prologue: stage W(0) + x(0,1); wr ends holding W(1)
    LDGW(0);
    XCP(0, 0);
    XCP(1, 1);
    CONVW(0);
    LDGW(1);
    cp_wait<1>();            // xs stage 0 ready
    __syncthreads();         // ws0 + xs0 visible

    for (int n = 0; n < nch; n++) {
        const int s2 = n & 1, s3 = n % 3;
        const uint32_t wsh = sb + WSH_OFF + s2 * 12800;
        const uint32_t wsl = sb + WSL_OFF + s2 * 12800;
        const uint32_t xsh = sb + XSH_OFF + s3 * 5120;
        const uint32_t xsl = sb + XSL_OFF + s3 * 5120;

        // fragment loads for both k16 halves up front
        uint32_t ah[2][2][4], al[2][2][4];
        uint32_t bh[2][5][2], bl[2][5][2];
#pragma unroll
        for (int kb = 0; kb < 2; kb++) {
#pragma unroll
            for (int mt = 0; mt < 2; mt++) {
                const uint32_t ao =
                    (uint32_t)(((wm * 32 + mt * 16 + a_ml) * 40 + kb * 16 + a_ko) * 2);
                ldsm4(ah[kb][mt], xsh + ao);
                ldsm4(al[kb][mt], xsl + ao);
            }
#pragma unroll
            for (int p = 0; p < 2; p++) {
                const uint32_t bo = (uint32_t)(
                    ((wn * 40 + (2 * p + b_p) * 8 + b_bn) * 40 + kb * 16 + b_ko) * 2);
                ldsm4(&bh[kb][2 * p][0], wsh + bo);
                ldsm4(&bl[kb][2 * p][0], wsl + bo);
            }
            const uint32_t bo = (uint32_t)(
                ((wn * 40 + 32 + b_bn) * 40 + kb * 16 + tC * 8) * 2);
            ldsm2(&bh[kb][4][0], wsh + bo);
            ldsm2(&bl[kb][4][0], wsl + bo);
        }

        // convert W(n+1) into the opposite stage — overlaps MMA issue below
        if (n + 1 < nch) CONVW(s2 ^ 1);

#pragma unroll
        for (int kb = 0; kb < 2; kb++) {
#pragma unroll
            for (int mt = 0; mt < 2; mt++)
#pragma unroll
                for (int nf = 0; nf < 5; nf++)
                    mma16816(acc[mt][nf], ah[kb][mt], bh[kb][nf]);
#pragma unroll
            for (int mt = 0; mt < 2; mt++)
#pragma unroll
                for (int nf = 0; nf < 5; nf++)
                    mma16816h(accC[mt][nf], ah[kb][mt], bl[kb][nf]);
#pragma unroll
            for (int mt = 0; mt < 2; mt++)
#pragma unroll
                for (int nf = 0; nf < 5; nf++)
                    mma16816h(accC[mt][nf], al[kb][mt], bh[kb][nf]);
        }

        if (n + 2 < nch) {
            LDGW(n + 2);             // refill wr after conversion consumed it
            XCP(n + 2, (n + 2) % 3); // stage was freed by chunk n-1
        }
        if (n + 1 < nch) cp_wait<1>();
        __syncthreads();             // publishes ws(s2^1) + orders xs reuse
    }

    // fold fp16 correction accs into fp32 accs
#pragma unroll
    for (int mt = 0; mt < 2; mt++)
#pragma unroll
        for (int nf = 0; nf < 5; nf++) {
            const __half2 c0 = *(const __half2*)&accC[mt][nf][0];
            const __half2 c1 = *(const __half2*)&accC[mt][nf][1];
            acc[mt][nf][0] += __low2float(c0);
            acc[mt][nf][1] += __high2float(c0);
            acc[mt][nf][2] += __low2float(c1);
            acc[mt][nf][3] += __high2float(c1);
        }

    // epilogue: g_part[j][b][i][co]
    float* base = g_part + (size_t)j * (B_ * IC_ * CO_) + (size_t)i * CO_;
#pragma unroll
    for (int mt = 0; mt < 2; mt++) {
        const int b = wm * 32 + mt * 16 + (lane >> 2);
#pragma unroll
        for (int nf = 0; nf < 5; nf++) {
            const int co = wn * 40 + nf * 8 + (lane & 3) * 2;
            float* d0 = base + (size_t)b * (IC_ * CO_) + co;
            *(float2*)d0 = make_float2(acc[mt][nf][0], acc[mt][nf][1]);
            *(float2*)(d0 + 8 * IC_ * CO_) =
                make_float2(acc[mt][nf][2], acc[mt][nf][3]);   // b+8
        }
    }
}

// ---------------------------------------------------------------------------
// 3) Fused split-K reduce + routing + v + fc partials + (last CTA) final pred.
// ---------------------------------------------------------------------------
#define ISTR 1032
__global__ __launch_bounds__(1024) void k_route_all(const float* __restrict__ fcw,
                                                    const float* __restrict__ fcb,
                                                    float* __restrict__ out) {
    extern __shared__ float sm[];
    float* u_s  = sm;                       // [16][ISTR]
    float* v_s  = sm + 16 * ISTR;           // [1024]
    float* csh  = v_s + 1024;               // [16]
    float* bijs = csh + 16;                 // [16]
    float* ared = bijs + 16;                // [32]
    __shared__ int last;
    const int c = blockIdx.x, t = threadIdx.x;

    {   // split-K reduce; i<8 has 19 splits, i>=8 has 18
        const int o4 = t & 3, i = (t >> 2) & 15, b0 = t >> 6;
        const int ns = (i < 8) ? 19 : 18;
#pragma unroll
        for (int jj = 0; jj < 4; jj++) {
            const int b = b0 + 16 * jj;
            const size_t off = ((size_t)b * IC_ + i) * CO_ + c * OC_ + o4 * 4;
            float4 s = make_float4(0.f, 0.f, 0.f, 0.f);
#pragma unroll 19
            for (int sp = 0; sp < ns; sp++) {
                float4 p = *(const float4*)(g_part + (size_t)sp * (B_ * IC_ * CO_) + off);
                s.x += p.x; s.y += p.y; s.z += p.z; s.w += p.w;
            }
            *(float4*)(u_s + i * ISTR + b * 16 + o4 * 4) = s;
        }
    }
    if (t < 16) bijs[t] = 0.f;
    __syncthreads();

    for (int it = 0; it < 3; it++) {
        if (t < 32) {   // softmax over i, width-16 shuffles
            float bv = (t < 16) ? bijs[t] : -1e30f;
            float m = bv;
#pragma unroll
            for (int off = 8; off; off >>= 1)
                m = fmaxf(m, __shfl_xor_sync(0xffffffffu, m, off, 16));
            float e = expf(bv - m), sum = e;
#pragma unroll
            for (int off = 8; off; off >>= 1)
                sum += __shfl_xor_sync(0xffffffffu, sum, off, 16);
            if (t < 16) csh[t] = e / sum;
        }
        __syncthreads();
        {
            float s = 0.f;
#pragma unroll
            for (int i = 0; i < IC_; i++) s += csh[i] * u_s[i * ISTR + t];
            v_s[t] = s * fabsf(s) / (1.f + s * s);
        }
        __syncthreads();
        if (it < 2) {   // agreement
            const int w = t >> 5, l = t & 31;
            const int i = w & 15, j0 = (w >> 4) * 512;
            float a = 0.f;
            for (int jj = j0 + l; jj < j0 + 512; jj += 32)
                a += u_s[i * ISTR + jj] * v_s[jj];
#pragma unroll
            for (int off = 16; off; off >>= 1)
                a += __shfl_down_sync(0xffffffffu, a, off);
            if (l == 0) ared[(w >> 4) * 16 + i] = a;
            __syncthreads();
            if (t < 16) bijs[t] += (ared[t] + ared[16 + t]) * (1.0f / B_);
            __syncthreads();
        }
    }
    {
        const int b = t >> 4, o = t & 15;
        const float v = v_s[t];
        out[B_ + b * CO_ + c * OC_ + o] = v;
        float p = v * fcw[c * OC_ + o];
#pragma unroll
        for (int off = 8; off; off >>= 1)
            p += __shfl_down_sync(0xffffffffu, p, off, 16);
        if (o == 0) g_fcp[c * B_ + b] = p;
    }
    __threadfence();
    if (t == 0) last = (atomicAdd(&g_ctr, 1) == NC_ - 1);
    __syncthreads();
    if (last) {
        if (t < B_) {
            float s = fcb[0];
#pragma unroll
            for (int cc = 0; cc < NC_; cc++) s += g_fcp[cc * B_ + t];
            out[t] = 1.f / (1.f + expf(-s));
        }
        if (t == 0) g_ctr = 0;   // reset for graph replay
    }
}

// ---------------------------------------------------------------------------
extern "C" void kernel_launch(void* const* d_in, const int* in_sizes, int n_in,
                              void* d_out, int out_size) {
    const float* x   = (const float*)d_in[0];
    const float* W   = (const float*)d_in[1];
    const float* fcw = (const float*)d_in[2];
    const float* fcb = (const float*)d_in[3];
    float* out = (float*)d_out;

    const int route_smem = (16 * ISTR + 1024 + 16 + 16 + 32) * 4;
    cudaFuncSetAttribute(k_gemm, cudaFuncAttributeMaxDynamicSharedMemorySize, SMEM_G);
    cudaFuncSetAttribute(k_route_all, cudaFuncAttributeMaxDynamicSharedMemorySize,
                         route_smem);

    k_transpose<<<dim3(NR_ / 256, B_), 256>>>(x);
    k_gemm<<<296, 256, SMEM_G>>>(W);
    k_route_all<<<NC_, 1024, route_smem>>>(fcw, fcb, out);
}

// round 15
// speedup vs baseline: 2.0462x; 2.0462x over previous
#include <cuda_runtime.h>
#include <cuda_fp16.h>
#include <cstdint>

#define B_   64
#define NR_  16384
#define IC_  16
#define NC_  10
#define OC_  16
#define CO_  160
#define KB   32
#define SMAX 19              // max splits per i (i<8: 19, i>=8: 18)

// -------- device scratch (no allocations allowed) --------
__device__ __half g_xhi[(size_t)IC_*B_*NR_];            // x hi fp16 [i][b][r]
__device__ __half g_xlo[(size_t)IC_*B_*NR_];            // x residual fp16
__device__ float g_part[(size_t)SMAX*B_*IC_*CO_];       // split-K partials [s][b][i][co]
__device__ float g_uhat[B_*IC_*CO_];                    // reduced u_hat
__device__ float g_fcp[NC_*B_];                         // fc partial dots [c][b]
__device__ int   g_ctr = 0;

// GEMM smem byte offsets (rows padded to 40 halves = 80B)
#define WSH_OFF 0            // W hi: 2 stages x 160x40 halves (12800/stage)
#define WSL_OFF 25600        // W lo
#define XSH_OFF 51200        // x hi: 4 stages x 64x40 halves (5120/stage)
#define XSL_OFF 71680        // x lo
#define SMEM_G  92160

static __device__ __forceinline__ void mma16816(float* c, const uint32_t* a,
                                                const uint32_t* b) {
    asm volatile(
        "mma.sync.aligned.m16n8k16.row.col.f32.f16.f16.f32 "
        "{%0,%1,%2,%3}, {%4,%5,%6,%7}, {%8,%9}, {%0,%1,%2,%3};"
        : "+f"(c[0]), "+f"(c[1]), "+f"(c[2]), "+f"(c[3])
        : "r"(a[0]), "r"(a[1]), "r"(a[2]), "r"(a[3]), "r"(b[0]), "r"(b[1]));
}
// fp16-accumulator variant (corrections)
static __device__ __forceinline__ void mma16816h(uint32_t* c, const uint32_t* a,
                                                 const uint32_t* b) {
    asm volatile(
        "mma.sync.aligned.m16n8k16.row.col.f16.f16.f16.f16 "
        "{%0,%1}, {%2,%3,%4,%5}, {%6,%7}, {%0,%1};"
        : "+r"(c[0]), "+r"(c[1])
        : "r"(a[0]), "r"(a[1]), "r"(a[2]), "r"(a[3]), "r"(b[0]), "r"(b[1]));
}
static __device__ __forceinline__ void ldsm4(uint32_t* r, uint32_t addr) {
    asm volatile("ldmatrix.sync.aligned.m8n8.x4.shared.b16 {%0,%1,%2,%3}, [%4];"
                 : "=r"(r[0]), "=r"(r[1]), "=r"(r[2]), "=r"(r[3]) : "r"(addr));
}
static __device__ __forceinline__ void ldsm2(uint32_t* r, uint32_t addr) {
    asm volatile("ldmatrix.sync.aligned.m8n8.x2.shared.b16 {%0,%1}, [%2];"
                 : "=r"(r[0]), "=r"(r[1]) : "r"(addr));
}
static __device__ __forceinline__ uint32_t smem_u32(const void* p) {
    uint32_t a;
    asm("{ .reg .u64 t; cvta.to.shared.u64 t, %1; cvt.u32.u64 %0, t; }"
        : "=r"(a) : "l"(p));
    return a;
}
static __device__ __forceinline__ void cp16(uint32_t dst, const void* src) {
    asm volatile("cp.async.cg.shared.global [%0], [%1], 16;" :: "r"(dst), "l"(src));
}
static __device__ __forceinline__ void cp_commit() {
    asm volatile("cp.async.commit_group;" ::: "memory");
}
template <int N> static __device__ __forceinline__ void cp_wait() {
    asm volatile("cp.async.wait_group %0;" :: "n"(N) : "memory");
}
static __device__ __forceinline__ void hsplit(float v, __half& h, __half& l) {
    h = __float2half_rn(v);
    l = __float2half_rn(v - __half2float(h));
}

// ---------------------------------------------------------------------------
// 1) Transpose + fp16 hi/lo split: x[b][r][i] -> g_xhi/g_xlo [i][b][r]
//    tile padded to 68 floats/row: write bank conflicts 4-way -> 2-way.
// ---------------------------------------------------------------------------
__global__ void k_transpose(const float* __restrict__ x) {
    __shared__ float tile[16][68];
    const int b = blockIdx.y, tid = threadIdx.x;
    const int r = tid >> 2, i4 = (tid & 3) * 4;
    const int i = tid >> 4, rs = (tid & 15) * 4;
    for (int tt = 0; tt < 4; tt++) {
        const int r0 = (blockIdx.x * 4 + tt) * 64;
        float4 v = *(const float4*)(x + ((size_t)b * NR_ + r0 + r) * IC_ + i4);
        tile[i4 + 0][r] = v.x; tile[i4 + 1][r] = v.y;
        tile[i4 + 2][r] = v.z; tile[i4 + 3][r] = v.w;
        __syncthreads();
        float4 o = *(const float4*)&tile[i][rs];
        union { __half h[4]; uint2 u; } ph, pl;
        hsplit(o.x, ph.h[0], pl.h[0]);
        hsplit(o.y, ph.h[1], pl.h[1]);
        hsplit(o.z, ph.h[2], pl.h[2]);
        hsplit(o.w, ph.h[3], pl.h[3]);
        const size_t dst = ((size_t)i * B_ + b) * NR_ + r0 + rs;
        *(uint2*)(g_xhi + dst) = ph.u;
        *(uint2*)(g_xlo + dst) = pl.u;
        __syncthreads();
    }
}

// ---------------------------------------------------------------------------
// 2) fp16x3 HMMA GEMM, 296 balanced CTAs. x has 4 cp.async stages so the
//    loop needs only ONE sync per chunk; W(n) conversion shares the barrier
//    interval with MMA(n-1) and overlaps it across warps.
// ---------------------------------------------------------------------------
__global__ __launch_bounds__(256, 2) void k_gemm(const float* __restrict__ Wg) {
    extern __shared__ char smem[];
    const uint32_t sb = smem_u32(smem);

    // CTA -> (i, split j, chunk range)
    int i, j, nch, st;
    {
        const int c = blockIdx.x;
        if (c < 152) {           // 8 i's x 19 splits
            i = c / 19; j = c - i * 19;
            nch = 26 + (j < 18); st = j * 26 + min(j, 18);
        } else {                 // 8 i's x 18 splits
            const int d = c - 152;
            const int q = d / 18;
            i = 8 + q; j = d - q * 18;
            nch = 28 + (j < 8);  st = j * 28 + min(j, 8);
        }
    }
    const int r0 = st * KB;
    const int t = threadIdx.x;
    const int warp = t >> 5, lane = t & 31;
    const int wm = warp >> 2, wn = warp & 3;
    const float* Wi = Wg + (size_t)i * CO_ * NR_;
    const __half* Xh = g_xhi + (size_t)i * B_ * NR_;
    const __half* Xl = g_xlo + (size_t)i * B_ * NR_;

    float acc[2][5][4];
    uint32_t accC[2][5][2];
#pragma unroll
    for (int m = 0; m < 2; m++)
#pragma unroll
        for (int n = 0; n < 5; n++) {
#pragma unroll
            for (int q = 0; q < 4; q++) acc[m][n][q] = 0.f;
            accC[m][n][0] = 0u; accC[m][n][1] = 0u;
        }

    const int tA = lane >> 3;
    const int a_ml = (tA & 1) * 8 + (lane & 7);
    const int a_ko = (tA >> 1) * 8;
    const int b_bn = lane & 7;
    const int b_ko = (tA & 1) * 8;
    const int b_p  = tA >> 1;
    const int tC   = (lane >> 3) & 1;

    const int wrow = t >> 3, wk4 = t & 7;
    float4 wr[5];

#define LDGW(nn) { \
        const float* wp = Wi + (size_t)wrow * NR_ + r0 + (nn) * KB + wk4 * 4; \
        _Pragma("unroll") \
        for (int q = 0; q < 5; q++) wr[q] = *(const float4*)(wp + (size_t)q * 32 * NR_); }

#define XCP(nn, ss) { \
        const int xrow = t >> 2, xk8 = (t & 3) * 8; \
        const size_t so = (size_t)xrow * NR_ + r0 + (nn) * KB + xk8; \
        const uint32_t d = (uint32_t)((xrow * 40 + xk8) * 2) + (ss) * 5120; \
        cp16(sb + XSH_OFF + d, Xh + so); \
        cp16(sb + XSL_OFF + d, Xl + so); \
        cp_commit(); }

    LDGW(0);
    XCP(0, 0);
    XCP(1, 1);

    for (int n = 0; n < nch; n++) {
        const int s2 = n & 1, s4 = n & 3;
        // convert W chunk n (regs) -> ws stage s2. Last reader of this stage
        // was compute(n-2), already closed by the sync of iteration n-1, so
        // no barrier is needed before this — it overlaps MMA(n-1) warps.
#pragma unroll
        for (int q = 0; q < 5; q++) {
            union { __half h[4]; uint2 u; } ph, pl;
            hsplit(wr[q].x, ph.h[0], pl.h[0]);
            hsplit(wr[q].y, ph.h[1], pl.h[1]);
            hsplit(wr[q].z, ph.h[2], pl.h[2]);
            hsplit(wr[q].w, ph.h[3], pl.h[3]);
            const uint32_t d = (uint32_t)(((wrow + q * 32) * 40 + wk4 * 4) * 2)
                             + s2 * 12800;
            *(uint2*)(smem + WSH_OFF + d) = ph.u;
            *(uint2*)(smem + WSL_OFF + d) = pl.u;
        }
        if (n + 1 < nch) LDGW(n + 1);
        if (n + 2 < nch) { XCP(n + 2, (n + 2) & 3); }   // stage free since n-2
        if (n + 2 < nch)      cp_wait<2>();
        else if (n + 1 < nch) cp_wait<1>();
        else                  cp_wait<0>();
        __syncthreads();                 // ws(s2) + xs(s4) ready, single sync

        const uint32_t wsh = sb + WSH_OFF + s2 * 12800;
        const uint32_t wsl = sb + WSL_OFF + s2 * 12800;
        const uint32_t xsh = sb + XSH_OFF + s4 * 5120;
        const uint32_t xsl = sb + XSL_OFF + s4 * 5120;
#pragma unroll
        for (int kb = 0; kb < 2; kb++) {
            uint32_t ah[2][4], al[2][4];
#pragma unroll
            for (int mt = 0; mt < 2; mt++) {
                const uint32_t ao =
                    (uint32_t)(((wm * 32 + mt * 16 + a_ml) * 40 + kb * 16 + a_ko) * 2);
                ldsm4(ah[mt], xsh + ao);
                ldsm4(al[mt], xsl + ao);
            }
            uint32_t bh[5][2], bl[5][2];
#pragma unroll
            for (int p = 0; p < 2; p++) {
                const uint32_t bo = (uint32_t)(
                    ((wn * 40 + (2 * p + b_p) * 8 + b_bn) * 40 + kb * 16 + b_ko) * 2);
                ldsm4(&bh[2 * p][0], wsh + bo);
                ldsm4(&bl[2 * p][0], wsl + bo);
            }
            {
                const uint32_t bo = (uint32_t)(
                    ((wn * 40 + 32 + b_bn) * 40 + kb * 16 + tC * 8) * 2);
                ldsm2(&bh[4][0], wsh + bo);
                ldsm2(&bl[4][0], wsl + bo);
            }
#pragma unroll
            for (int mt = 0; mt < 2; mt++)
#pragma unroll
                for (int nf = 0; nf < 5; nf++) mma16816(acc[mt][nf], ah[mt], bh[nf]);
#pragma unroll
            for (int mt = 0; mt < 2; mt++)
#pragma unroll
                for (int nf = 0; nf < 5; nf++) mma16816h(accC[mt][nf], ah[mt], bl[nf]);
#pragma unroll
            for (int mt = 0; mt < 2; mt++)
#pragma unroll
                for (int nf = 0; nf < 5; nf++) mma16816h(accC[mt][nf], al[mt], bh[nf]);
        }
    }

    // fold fp16 correction accs into fp32 accs
#pragma unroll
    for (int mt = 0; mt < 2; mt++)
#pragma unroll
        for (int nf = 0; nf < 5; nf++) {
            const __half2 c0 = *(const __half2*)&accC[mt][nf][0];
            const __half2 c1 = *(const __half2*)&accC[mt][nf][1];
            acc[mt][nf][0] += __low2float(c0);
            acc[mt][nf][1] += __high2float(c0);
            acc[mt][nf][2] += __low2float(c1);
            acc[mt][nf][3] += __high2float(c1);
        }

    // epilogue: g_part[j][b][i][co]
    float* base = g_part + (size_t)j * (B_ * IC_ * CO_) + (size_t)i * CO_;
#pragma unroll
    for (int mt = 0; mt < 2; mt++) {
        const int b = wm * 32 + mt * 16 + (lane >> 2);
#pragma unroll
        for (int nf = 0; nf < 5; nf++) {
            const int co = wn * 40 + nf * 8 + (lane & 3) * 2;
            float* d0 = base + (size_t)b * (IC_ * CO_) + co;
            *(float2*)d0 = make_float2(acc[mt][nf][0], acc[mt][nf][1]);
            *(float2*)(d0 + 8 * IC_ * CO_) =
                make_float2(acc[mt][nf][2], acc[mt][nf][3]);   // b+8
        }
    }
}

// ---------------------------------------------------------------------------
// 3) Whole-chip split-K reduce: g_part -> g_uhat (160 CTAs, float4/thread)
// ---------------------------------------------------------------------------
__global__ void k_reduce() {
    const int idx4 = blockIdx.x * blockDim.x + threadIdx.x;   // float4 index
    const int idx = idx4 * 4;
    const int i = (idx / CO_) & 15;
    const int ns = (i < 8) ? 19 : 18;
    float4 s = make_float4(0.f, 0.f, 0.f, 0.f);
#pragma unroll 19
    for (int sp = 0; sp < ns; sp++) {
        float4 p = *(const float4*)(g_part + (size_t)sp * (B_ * IC_ * CO_) + idx);
        s.x += p.x; s.y += p.y; s.z += p.z; s.w += p.w;
    }
    *(float4*)(g_uhat + idx) = s;
}

// ---------------------------------------------------------------------------
// 4) Routing (3 iters) + v + fc partials + (last CTA) final pred.
// ---------------------------------------------------------------------------
#define ISTR 1032
__global__ __launch_bounds__(1024) void k_route_all(const float* __restrict__ fcw,
                                                    const float* __restrict__ fcb,
                                                    float* __restrict__ out) {
    extern __shared__ float sm[];
    float* u_s  = sm;                       // [16][ISTR]
    float* v_s  = sm + 16 * ISTR;           // [1024]
    float* csh  = v_s + 1024;               // [16]
    float* bijs = csh + 16;                 // [16]
    float* ared = bijs + 16;                // [32]
    __shared__ int last;
    const int c = blockIdx.x, t = threadIdx.x;

    {   // load u_hat slice for this capsule
        const int o4 = t & 3, i = (t >> 2) & 15, b0 = t >> 6;
#pragma unroll
        for (int jj = 0; jj < 4; jj++) {
            const int b = b0 + 16 * jj;
            float4 p = *(const float4*)(g_uhat + ((size_t)b * IC_ + i) * CO_
                                        + c * OC_ + o4 * 4);
            *(float4*)(u_s + i * ISTR + b * 16 + o4 * 4) = p;
        }
    }
    if (t < 16) bijs[t] = 0.f;
    __syncthreads();

    for (int it = 0; it < 3; it++) {
        if (t < 32) {   // softmax over i, width-16 shuffles
            float bv = (t < 16) ? bijs[t] : -1e30f;
            float m = bv;
#pragma unroll
            for (int off = 8; off; off >>= 1)
                m = fmaxf(m, __shfl_xor_sync(0xffffffffu, m, off, 16));
            float e = expf(bv - m), sum = e;
#pragma unroll
            for (int off = 8; off; off >>= 1)
                sum += __shfl_xor_sync(0xffffffffu, sum, off, 16);
            if (t < 16) csh[t] = e / sum;
        }
        __syncthreads();
        {
            float s = 0.f;
#pragma unroll
            for (int i = 0; i < IC_; i++) s += csh[i] * u_s[i * ISTR + t];
            v_s[t] = s * fabsf(s) / (1.f + s * s);
        }
        __syncthreads();
        if (it < 2) {   // agreement
            const int w = t >> 5, l = t & 31;
            const int i = w & 15, j0 = (w >> 4) * 512;
            float a = 0.f;
            for (int jj = j0 + l; jj < j0 + 512; jj += 32)
                a += u_s[i * ISTR + jj] * v_s[jj];
#pragma unroll
            for (int off = 16; off; off >>= 1)
                a += __shfl_down_sync(0xffffffffu, a, off);
            if (l == 0) ared[(w >> 4) * 16 + i] = a;
            __syncthreads();
            if (t < 16) bijs[t] += (ared[t] + ared[16 + t]) * (1.0f / B_);
            __syncthreads();
        }
    }
    {
        const int b = t >> 4, o = t & 15;
        const float v = v_s[t];
        out[B_ + b * CO_ + c * OC_ + o] = v;
        float p = v * fcw[c * OC_ + o];
#pragma unroll
        for (int off = 8; off; off >>= 1)
            p += __shfl_down_sync(0xffffffffu, p, off, 16);
        if (o == 0) g_fcp[c * B_ + b] = p;
    }
    __threadfence();
    if (t == 0) last = (atomicAdd(&g_ctr, 1) == NC_ - 1);
    __syncthreads();
    if (last) {
        if (t < B_) {
            float s = fcb[0];
#pragma unroll
            for (int cc = 0; cc < NC_; cc++) s += g_fcp[cc * B_ + t];
            out[t] = 1.f / (1.f + expf(-s));
        }
        if (t == 0) g_ctr = 0;   // reset for graph replay
    }
}

// ---------------------------------------------------------------------------
extern "C" void kernel_launch(void* const* d_in, const int* in_sizes, int n_in,
                              void* d_out, int out_size) {
    const float* x   = (const float*)d_in[0];
    const float* W   = (const float*)d_in[1];
    const float* fcw = (const float*)d_in[2];
    const float* fcb = (const float*)d_in[3];
    float* out = (float*)d_out;

    const int route_smem = (16 * ISTR + 1024 + 16 + 16 + 32) * 4;
    cudaFuncSetAttribute(k_gemm, cudaFuncAttributeMaxDynamicSharedMemorySize, SMEM_G);
    cudaFuncSetAttribute(k_route_all, cudaFuncAttributeMaxDynamicSharedMemorySize,
                         route_smem);

    k_transpose<<<dim3(NR_ / 256, B_), 256>>>(x);
    k_gemm<<<296, 256, SMEM_G>>>(W);
    k_reduce<<<(B_ * IC_ * CO_) / 4 / 256, 256>>>();
    k_route_all<<<NC_, 1024, route_smem>>>(fcw, fcb, out);
}